// round 12
// baseline (speedup 1.0000x reference)
#include <cuda_runtime.h>
#include <cuda_bf16.h>

typedef unsigned int u32;
typedef unsigned long long u64;

#define M_TOT   16384
#define HID     1024
#define INTERF  4096

// ---------------- device scratch (allocation-free: __device__ globals) ------
__device__ __nv_bfloat16 g_Xhi [M_TOT * HID];
__device__ __nv_bfloat16 g_Xlo [M_TOT * HID];
__device__ __nv_bfloat16 g_W1hi[INTERF * HID];
__device__ __nv_bfloat16 g_W1lo[INTERF * HID];
__device__ __nv_bfloat16 g_W2hi[HID * INTERF];
__device__ __nv_bfloat16 g_W2lo[HID * INTERF];
__device__ __nv_bfloat16 g_Ahi [M_TOT * INTERF];
__device__ __nv_bfloat16 g_Alo [M_TOT * INTERF];

// ---------------- baseline-PTX helpers (no 'a'-gated features) --------------
__device__ __forceinline__ u32 smem_u32(const void* p) {
    return (u32)__cvta_generic_to_shared(p);
}

__device__ __forceinline__ void cp16(u32 dst, const void* src) {
    asm volatile("cp.async.cg.shared.global [%0], [%1], 16;\n" :: "r"(dst), "l"(src));
}
#define CP_COMMIT() asm volatile("cp.async.commit_group;\n" ::: "memory")
#define CP_WAIT(n)  asm volatile("cp.async.wait_group %0;\n" :: "n"(n) : "memory")

__device__ __forceinline__ void ldsm4(u32* r, u32 addr) {
    asm volatile("ldmatrix.sync.aligned.m8n8.x4.shared.b16 {%0,%1,%2,%3}, [%4];\n"
                 : "=r"(r[0]), "=r"(r[1]), "=r"(r[2]), "=r"(r[3]) : "r"(addr));
}

__device__ __forceinline__ void mma16816(float* d, const u32* a, u32 b0, u32 b1) {
    asm volatile(
        "mma.sync.aligned.m16n8k16.row.col.f32.bf16.bf16.f32 "
        "{%0,%1,%2,%3}, {%4,%5,%6,%7}, {%8,%9}, {%0,%1,%2,%3};\n"
        : "+f"(d[0]), "+f"(d[1]), "+f"(d[2]), "+f"(d[3])
        : "r"(a[0]), "r"(a[1]), "r"(a[2]), "r"(a[3]), "r"(b0), "r"(b1));
}

__device__ __forceinline__ u32 pack_bf2(__nv_bfloat16 a, __nv_bfloat16 b) {
    return (u32)__bfloat16_as_ushort(a) | ((u32)__bfloat16_as_ushort(b) << 16);
}

// ---------------- split kernel: f32 -> bf16 hi/lo planes --------------------
__global__ void split_kernel(const float* __restrict__ in,
                             __nv_bfloat16* __restrict__ hi,
                             __nv_bfloat16* __restrict__ lo, int n4) {
    int i = blockIdx.x * blockDim.x + threadIdx.x;
    if (i >= n4) return;
    float4 v = ((const float4*)in)[i];
    __nv_bfloat16 h0 = __float2bfloat16(v.x);
    __nv_bfloat16 h1 = __float2bfloat16(v.y);
    __nv_bfloat16 h2 = __float2bfloat16(v.z);
    __nv_bfloat16 h3 = __float2bfloat16(v.w);
    u32 hp0 = pack_bf2(h0, h1), hp1 = pack_bf2(h2, h3);
    u32 lp0 = pack_bf2(__float2bfloat16(v.x - __bfloat162float(h0)),
                       __float2bfloat16(v.y - __bfloat162float(h1)));
    u32 lp1 = pack_bf2(__float2bfloat16(v.z - __bfloat162float(h2)),
                       __float2bfloat16(v.w - __bfloat162float(h3)));
    ((uint2*)hi)[i] = make_uint2(hp0, hp1);
    ((uint2*)lo)[i] = make_uint2(lp0, lp1);
}

// ---------------- fused GEMM: C = Ahi*Bhi^T + Alo*Bhi^T + Ahi*Blo^T + bias --
// CTA 256x128, 512 threads (16 warps: 4M x 4N, warp tile 64x32).
// K-chunk 32, 3-stage cp.async pipeline, ONE __syncthreads per chunk.
// Smem rows padded to 80B stride -> conflict-free ldmatrix.
// MODE 0: relu + re-split -> outHi/outLo bf16 planes (layer 1)
// MODE 1: f32 store -> outF (layer 2)

#define STAGES    3
#define ROW_B     80
#define A_TILE_B  (256 * ROW_B)                 // 20480
#define B_TILE_B  (128 * ROW_B)                 // 10240
#define OFF_AHI   0
#define OFF_ALO   (A_TILE_B)
#define OFF_BHI   (2 * A_TILE_B)
#define OFF_BLO   (2 * A_TILE_B + B_TILE_B)
#define STAGE_B   (2 * A_TILE_B + 2 * B_TILE_B) // 61440
#define SMEM_BYTES (STAGES * STAGE_B)           // 184320

template <int MODE>
__global__ void __launch_bounds__(512, 1) ffn_gemm_kernel(
    const __nv_bfloat16* __restrict__ Ahi, const __nv_bfloat16* __restrict__ Alo,
    const __nv_bfloat16* __restrict__ Bhi, const __nv_bfloat16* __restrict__ Blo,
    const float* __restrict__ bias,
    __nv_bfloat16* __restrict__ outHi, __nv_bfloat16* __restrict__ outLo,
    float* __restrict__ outF,
    int N, int K)
{
    extern __shared__ char smem[];
    const u32 sbase = smem_u32(smem);
    const int tid  = threadIdx.x;
    const int wid  = tid >> 5;
    const int lane = tid & 31;
    const int wm   = wid & 3;        // M: 4 warps x 64
    const int wn   = wid >> 2;       // N: 4 warps x 32
    const int n0   = blockIdx.x * 128;
    const int m0   = blockIdx.y * 256;

    // per-thread gmem load coords: 512 threads cover 128 rows x 4 x 16B chunks
    const int rld = tid >> 2;              // row 0..127
    const int cld = tid & 3;               // 16B chunk within 64B row

    const int nchunks = K >> 5;

    auto load_chunk = [&](int s, int kc) {
        const int k0 = kc << 5;
        const u32 st = sbase + s * STAGE_B;
        const u32 so = (u32)(rld * ROW_B + cld * 16);
        const size_t koff = (size_t)(k0 + cld * 8);
        // A: 256 rows (two 128-row halves), hi+lo planes
        #pragma unroll
        for (int h = 0; h < 2; h++) {
            const int r = rld + h * 128;
            const size_t ga = (size_t)(m0 + r) * (size_t)K + koff;
            const u32 soh = so + (u32)(h * 128 * ROW_B);
            cp16(st + OFF_AHI + soh, Ahi + ga);
            cp16(st + OFF_ALO + soh, Alo + ga);
        }
        // B: 128 rows, hi+lo planes
        {
            const size_t gb = (size_t)(n0 + rld) * (size_t)K + koff;
            cp16(st + OFF_BHI + so, Bhi + gb);
            cp16(st + OFF_BLO + so, Blo + gb);
        }
    };

    float acc[4][4][4];
    #pragma unroll
    for (int i = 0; i < 4; i++)
        #pragma unroll
        for (int j = 0; j < 4; j++)
            #pragma unroll
            for (int q = 0; q < 4; q++) acc[i][j][q] = 0.0f;

    // prologue: fill STAGES-1 stages
    #pragma unroll
    for (int s = 0; s < STAGES - 1; s++) {
        load_chunk(s, s);
        CP_COMMIT();
    }

    const int a_row = (lane & 15);
    const int colhi = (lane >> 4) * 16;     // 0 or 16 bytes (k half)

    for (int kc = 0; kc < nchunks; kc++) {
        CP_WAIT(STAGES - 2);
        __syncthreads();

        {   // issue loads for chunk kc+STAGES-1 (slot != read slot, != WAR slot)
            const int ld = kc + STAGES - 1;
            if (ld < nchunks) load_chunk(ld % STAGES, ld);
            CP_COMMIT();
        }

        const u32 st  = sbase + (kc % STAGES) * STAGE_B;
        const u32 sAh = st + OFF_AHI;
        const u32 sAl = st + OFF_ALO;
        const u32 sBh = st + OFF_BHI;
        const u32 sBl = st + OFF_BLO;

        #pragma unroll
        for (int ks = 0; ks < 2; ks++) {
            const int cb = ks * 32 + colhi;
            u32 bh[2][4], bl[2][4];
            #pragma unroll
            for (int j2 = 0; j2 < 2; j2++) {
                const u32 ro = (u32)((wn * 32 + j2 * 16 + a_row) * ROW_B + cb);
                ldsm4(bh[j2], sBh + ro);
                ldsm4(bl[j2], sBl + ro);
            }
            #pragma unroll
            for (int mp = 0; mp < 2; mp++) {     // process mi in pairs: lower regs
                u32 ah[2][4], al[2][4];
                #pragma unroll
                for (int i = 0; i < 2; i++) {
                    const int mi = mp * 2 + i;
                    const u32 ro = (u32)((wm * 64 + mi * 16 + a_row) * ROW_B + cb);
                    ldsm4(ah[i], sAh + ro);
                    ldsm4(al[i], sAl + ro);
                }
                #pragma unroll
                for (int i = 0; i < 2; i++) {
                    const int mi = mp * 2 + i;
                    #pragma unroll
                    for (int nj = 0; nj < 4; nj++) {
                        const int j2 = nj >> 1, sl = nj & 1;
                        mma16816(acc[mi][nj], ah[i], bh[j2][sl], bh[j2][sl + 2]); // hi*hi
                        mma16816(acc[mi][nj], al[i], bh[j2][sl], bh[j2][sl + 2]); // lo*hi
                        mma16816(acc[mi][nj], ah[i], bl[j2][sl], bl[j2][sl + 2]); // hi*lo
                    }
                }
            }
        }
        // no trailing sync: top-of-iteration barrier prevents WAR across iters
    }

    // ---------------- epilogue ----------------
    // acc[mi][nj]: d0=(r,c) d1=(r,c+1) d2=(r+8,c) d3=(r+8,c+1)
    const int er = lane >> 2;
    const int ec = (lane & 3) * 2;
    #pragma unroll
    for (int nj = 0; nj < 4; nj++) {
        const int col = n0 + wn * 32 + nj * 8 + ec;
        const float2 bz = __ldg((const float2*)(bias + col));
        #pragma unroll
        for (int mi = 0; mi < 4; mi++) {
            const int row = m0 + wm * 64 + mi * 16 + er;
            #pragma unroll
            for (int half = 0; half < 2; half++) {
                const int rr = row + half * 8;
                float v0 = acc[mi][nj][half * 2 + 0] + bz.x;
                float v1 = acc[mi][nj][half * 2 + 1] + bz.y;
                if (MODE == 0) {
                    v0 = fmaxf(v0, 0.0f);
                    v1 = fmaxf(v1, 0.0f);
                    __nv_bfloat16 h0 = __float2bfloat16(v0);
                    __nv_bfloat16 h1 = __float2bfloat16(v1);
                    __nv_bfloat16 l0 = __float2bfloat16(v0 - __bfloat162float(h0));
                    __nv_bfloat16 l1 = __float2bfloat16(v1 - __bfloat162float(h1));
                    const size_t o = (size_t)rr * (size_t)N + col;
                    *(u32*)(outHi + o) = pack_bf2(h0, h1);
                    *(u32*)(outLo + o) = pack_bf2(l0, l1);
                } else {
                    const size_t o = (size_t)rr * (size_t)N + col;
                    *(float2*)(outF + o) = make_float2(v0, v1);
                }
            }
        }
    }
}

// ---------------- launch ----------------------------------------------------
extern "C" void kernel_launch(void* const* d_in, const int* in_sizes, int n_in,
                              void* d_out, int out_size) {
    const float* X  = (const float*)d_in[0];
    const float* W1 = (const float*)d_in[1];
    const float* b1 = (const float*)d_in[2];
    const float* W2 = (const float*)d_in[3];
    const float* b2 = (const float*)d_in[4];
    float* out = (float*)d_out;

    void *xh, *xl, *w1h, *w1l, *w2h, *w2l, *ah, *al;
    cudaGetSymbolAddress(&xh,  g_Xhi);
    cudaGetSymbolAddress(&xl,  g_Xlo);
    cudaGetSymbolAddress(&w1h, g_W1hi);
    cudaGetSymbolAddress(&w1l, g_W1lo);
    cudaGetSymbolAddress(&w2h, g_W2hi);
    cudaGetSymbolAddress(&w2l, g_W2lo);
    cudaGetSymbolAddress(&ah,  g_Ahi);
    cudaGetSymbolAddress(&al,  g_Alo);

    cudaFuncSetAttribute(ffn_gemm_kernel<0>, cudaFuncAttributeMaxDynamicSharedMemorySize, SMEM_BYTES);
    cudaFuncSetAttribute(ffn_gemm_kernel<1>, cudaFuncAttributeMaxDynamicSharedMemorySize, SMEM_BYTES);

    {
        int n4 = M_TOT * HID / 4;
        split_kernel<<<(n4 + 255) / 256, 256>>>(X, (__nv_bfloat16*)xh, (__nv_bfloat16*)xl, n4);
    }
    {
        int n4 = INTERF * HID / 4;
        split_kernel<<<(n4 + 255) / 256, 256>>>(W1, (__nv_bfloat16*)w1h, (__nv_bfloat16*)w1l, n4);
    }
    {
        int n4 = HID * INTERF / 4;
        split_kernel<<<(n4 + 255) / 256, 256>>>(W2, (__nv_bfloat16*)w2h, (__nv_bfloat16*)w2l, n4);
    }

    // Layer 1: inter = relu(X @ W1^T + b1)  -> split bf16 planes
    dim3 g1(INTERF / 128, M_TOT / 256);
    ffn_gemm_kernel<0><<<g1, 512, SMEM_BYTES>>>(
        (const __nv_bfloat16*)xh, (const __nv_bfloat16*)xl,
        (const __nv_bfloat16*)w1h, (const __nv_bfloat16*)w1l,
        b1,
        (__nv_bfloat16*)ah, (__nv_bfloat16*)al, (float*)nullptr,
        INTERF, HID);

    // Layer 2: out = act @ W2^T + b2  -> f32
    dim3 g2(HID / 128, M_TOT / 256);
    ffn_gemm_kernel<1><<<g2, 512, SMEM_BYTES>>>(
        (const __nv_bfloat16*)ah, (const __nv_bfloat16*)al,
        (const __nv_bfloat16*)w2h, (const __nv_bfloat16*)w2l,
        b2,
        (__nv_bfloat16*)nullptr, (__nv_bfloat16*)nullptr, out,
        HID, INTERF);
}

// round 13
// speedup vs baseline: 1.0197x; 1.0197x over previous
#include <cuda_runtime.h>
#include <cuda_bf16.h>

typedef unsigned int u32;
typedef unsigned long long u64;

#define M_TOT   16384
#define HID     1024
#define INTERF  4096

// ---------------- device scratch (allocation-free: __device__ globals) ------
__device__ __nv_bfloat16 g_Xhi [M_TOT * HID];
__device__ __nv_bfloat16 g_Xlo [M_TOT * HID];
__device__ __nv_bfloat16 g_W1hi[INTERF * HID];
__device__ __nv_bfloat16 g_W1lo[INTERF * HID];
__device__ __nv_bfloat16 g_W2hi[HID * INTERF];
__device__ __nv_bfloat16 g_W2lo[HID * INTERF];
__device__ __nv_bfloat16 g_Ahi [M_TOT * INTERF];
__device__ __nv_bfloat16 g_Alo [M_TOT * INTERF];

// ---------------- baseline-PTX helpers (no 'a'-gated features) --------------
__device__ __forceinline__ u32 smem_u32(const void* p) {
    return (u32)__cvta_generic_to_shared(p);
}

__device__ __forceinline__ void cp16(u32 dst, const void* src) {
    asm volatile("cp.async.cg.shared.global [%0], [%1], 16;\n" :: "r"(dst), "l"(src));
}
#define CP_COMMIT() asm volatile("cp.async.commit_group;\n" ::: "memory")
#define CP_WAIT(n)  asm volatile("cp.async.wait_group %0;\n" :: "n"(n) : "memory")

__device__ __forceinline__ void ldsm4(u32* r, u32 addr) {
    asm volatile("ldmatrix.sync.aligned.m8n8.x4.shared.b16 {%0,%1,%2,%3}, [%4];\n"
                 : "=r"(r[0]), "=r"(r[1]), "=r"(r[2]), "=r"(r[3]) : "r"(addr));
}

__device__ __forceinline__ void mma16816(float* d, const u32* a, u32 b0, u32 b1) {
    asm volatile(
        "mma.sync.aligned.m16n8k16.row.col.f32.bf16.bf16.f32 "
        "{%0,%1,%2,%3}, {%4,%5,%6,%7}, {%8,%9}, {%0,%1,%2,%3};\n"
        : "+f"(d[0]), "+f"(d[1]), "+f"(d[2]), "+f"(d[3])
        : "r"(a[0]), "r"(a[1]), "r"(a[2]), "r"(a[3]), "r"(b0), "r"(b1));
}

__device__ __forceinline__ u32 pack_bf2(__nv_bfloat16 a, __nv_bfloat16 b) {
    return (u32)__bfloat16_as_ushort(a) | ((u32)__bfloat16_as_ushort(b) << 16);
}

// ---------------- split kernel: f32 -> bf16 hi/lo planes --------------------
__global__ void split_kernel(const float* __restrict__ in,
                             __nv_bfloat16* __restrict__ hi,
                             __nv_bfloat16* __restrict__ lo, int n4) {
    int i = blockIdx.x * blockDim.x + threadIdx.x;
    if (i >= n4) return;
    float4 v = ((const float4*)in)[i];
    __nv_bfloat16 h0 = __float2bfloat16(v.x);
    __nv_bfloat16 h1 = __float2bfloat16(v.y);
    __nv_bfloat16 h2 = __float2bfloat16(v.z);
    __nv_bfloat16 h3 = __float2bfloat16(v.w);
    u32 hp0 = pack_bf2(h0, h1), hp1 = pack_bf2(h2, h3);
    u32 lp0 = pack_bf2(__float2bfloat16(v.x - __bfloat162float(h0)),
                       __float2bfloat16(v.y - __bfloat162float(h1)));
    u32 lp1 = pack_bf2(__float2bfloat16(v.z - __bfloat162float(h2)),
                       __float2bfloat16(v.w - __bfloat162float(h3)));
    ((uint2*)hi)[i] = make_uint2(hp0, hp1);
    ((uint2*)lo)[i] = make_uint2(lp0, lp1);
}

// ---------------- fused GEMM: C = Ahi*Bhi^T + Alo*Bhi^T + Ahi*Blo^T + bias --
// CTA 256x128, 512 threads (16 warps: 4M x 4N, warp tile 64x32).
// K-chunk 32, 3-stage cp.async pipeline, ONE __syncthreads per chunk.
// COMBO-MAJOR mma ordering: 8 independent HMMAs between accumulator reuse.
// Smem rows padded to 80B stride -> conflict-free ldmatrix.
// MODE 0: relu + re-split -> outHi/outLo bf16 planes (layer 1)
// MODE 1: f32 store -> outF (layer 2)

#define STAGES    3
#define ROW_B     80
#define A_TILE_B  (256 * ROW_B)                 // 20480
#define B_TILE_B  (128 * ROW_B)                 // 10240
#define OFF_AHI   0
#define OFF_ALO   (A_TILE_B)
#define OFF_BHI   (2 * A_TILE_B)
#define OFF_BLO   (2 * A_TILE_B + B_TILE_B)
#define STAGE_B   (2 * A_TILE_B + 2 * B_TILE_B) // 61440
#define SMEM_BYTES (STAGES * STAGE_B)           // 184320

template <int MODE>
__global__ void __launch_bounds__(512, 1) ffn_gemm_kernel(
    const __nv_bfloat16* __restrict__ Ahi, const __nv_bfloat16* __restrict__ Alo,
    const __nv_bfloat16* __restrict__ Bhi, const __nv_bfloat16* __restrict__ Blo,
    const float* __restrict__ bias,
    __nv_bfloat16* __restrict__ outHi, __nv_bfloat16* __restrict__ outLo,
    float* __restrict__ outF,
    int N, int K)
{
    extern __shared__ char smem[];
    const u32 sbase = smem_u32(smem);
    const int tid  = threadIdx.x;
    const int wid  = tid >> 5;
    const int lane = tid & 31;
    const int wm   = wid & 3;        // M: 4 warps x 64
    const int wn   = wid >> 2;       // N: 4 warps x 32
    const int n0   = blockIdx.x * 128;
    const int m0   = blockIdx.y * 256;

    // per-thread gmem load coords: 512 threads cover 128 rows x 4 x 16B chunks
    const int rld = tid >> 2;              // row 0..127
    const int cld = tid & 3;               // 16B chunk within 64B row

    const int nchunks = K >> 5;

    auto load_chunk = [&](int s, int kc) {
        const int k0 = kc << 5;
        const u32 st = sbase + s * STAGE_B;
        const u32 so = (u32)(rld * ROW_B + cld * 16);
        const size_t koff = (size_t)(k0 + cld * 8);
        #pragma unroll
        for (int h = 0; h < 2; h++) {
            const int r = rld + h * 128;
            const size_t ga = (size_t)(m0 + r) * (size_t)K + koff;
            const u32 soh = so + (u32)(h * 128 * ROW_B);
            cp16(st + OFF_AHI + soh, Ahi + ga);
            cp16(st + OFF_ALO + soh, Alo + ga);
        }
        {
            const size_t gb = (size_t)(n0 + rld) * (size_t)K + koff;
            cp16(st + OFF_BHI + so, Bhi + gb);
            cp16(st + OFF_BLO + so, Blo + gb);
        }
    };

    float acc[4][4][4];
    #pragma unroll
    for (int i = 0; i < 4; i++)
        #pragma unroll
        for (int j = 0; j < 4; j++)
            #pragma unroll
            for (int q = 0; q < 4; q++) acc[i][j][q] = 0.0f;

    // prologue: fill STAGES-1 stages
    #pragma unroll
    for (int s = 0; s < STAGES - 1; s++) {
        load_chunk(s, s);
        CP_COMMIT();
    }

    const int a_row = (lane & 15);
    const int colhi = (lane >> 4) * 16;     // 0 or 16 bytes (k half)
    // hoisted ldmatrix base offsets (row component)
    const u32 aoff = (u32)((wm * 64 + a_row) * ROW_B);
    const u32 boff = (u32)((wn * 32 + a_row) * ROW_B);

    for (int kc = 0; kc < nchunks; kc++) {
        CP_WAIT(STAGES - 2);
        __syncthreads();

        {   // issue loads for chunk kc+STAGES-1 (slot != read slot, != WAR slot)
            const int ld = kc + STAGES - 1;
            if (ld < nchunks) load_chunk(ld % STAGES, ld);
            CP_COMMIT();
        }

        const u32 st  = sbase + (kc % STAGES) * STAGE_B;
        const u32 sAh = st + OFF_AHI + aoff;
        const u32 sAl = st + OFF_ALO + aoff;
        const u32 sBh = st + OFF_BHI + boff;
        const u32 sBl = st + OFF_BLO + boff;

        #pragma unroll
        for (int ks = 0; ks < 2; ks++) {
            const int cb = ks * 32 + colhi;
            u32 bh[2][4], bl[2][4];
            #pragma unroll
            for (int j2 = 0; j2 < 2; j2++) {
                const u32 ro = (u32)(j2 * 16 * ROW_B + cb);
                ldsm4(bh[j2], sBh + ro);
                ldsm4(bl[j2], sBl + ro);
            }
            #pragma unroll
            for (int mp = 0; mp < 2; mp++) {     // mi pairs: bounded live regs
                u32 ah[2][4], al[2][4];
                #pragma unroll
                for (int i = 0; i < 2; i++) {
                    const u32 ro = (u32)(((mp * 2 + i) * 16) * ROW_B + cb);
                    ldsm4(ah[i], sAh + ro);
                    ldsm4(al[i], sAl + ro);
                }
                // ---- combo-major: 8 independent HMMAs between acc reuse ----
                #pragma unroll
                for (int i = 0; i < 2; i++)          // hi*hi
                    #pragma unroll
                    for (int nj = 0; nj < 4; nj++) {
                        const int j2 = nj >> 1, sl = nj & 1;
                        mma16816(acc[mp * 2 + i][nj], ah[i], bh[j2][sl], bh[j2][sl + 2]);
                    }
                #pragma unroll
                for (int i = 0; i < 2; i++)          // lo*hi
                    #pragma unroll
                    for (int nj = 0; nj < 4; nj++) {
                        const int j2 = nj >> 1, sl = nj & 1;
                        mma16816(acc[mp * 2 + i][nj], al[i], bh[j2][sl], bh[j2][sl + 2]);
                    }
                #pragma unroll
                for (int i = 0; i < 2; i++)          // hi*lo
                    #pragma unroll
                    for (int nj = 0; nj < 4; nj++) {
                        const int j2 = nj >> 1, sl = nj & 1;
                        mma16816(acc[mp * 2 + i][nj], ah[i], bl[j2][sl], bl[j2][sl + 2]);
                    }
            }
        }
        // no trailing sync: top-of-iteration barrier prevents WAR across iters
    }

    // ---------------- epilogue ----------------
    // acc[mi][nj]: d0=(r,c) d1=(r,c+1) d2=(r+8,c) d3=(r+8,c+1)
    const int er = lane >> 2;
    const int ec = (lane & 3) * 2;
    #pragma unroll
    for (int nj = 0; nj < 4; nj++) {
        const int col = n0 + wn * 32 + nj * 8 + ec;
        const float2 bz = __ldg((const float2*)(bias + col));
        #pragma unroll
        for (int mi = 0; mi < 4; mi++) {
            const int row = m0 + wm * 64 + mi * 16 + er;
            #pragma unroll
            for (int half = 0; half < 2; half++) {
                const int rr = row + half * 8;
                float v0 = acc[mi][nj][half * 2 + 0] + bz.x;
                float v1 = acc[mi][nj][half * 2 + 1] + bz.y;
                if (MODE == 0) {
                    v0 = fmaxf(v0, 0.0f);
                    v1 = fmaxf(v1, 0.0f);
                    __nv_bfloat16 h0 = __float2bfloat16(v0);
                    __nv_bfloat16 h1 = __float2bfloat16(v1);
                    __nv_bfloat16 l0 = __float2bfloat16(v0 - __bfloat162float(h0));
                    __nv_bfloat16 l1 = __float2bfloat16(v1 - __bfloat162float(h1));
                    const size_t o = (size_t)rr * (size_t)N + col;
                    *(u32*)(outHi + o) = pack_bf2(h0, h1);
                    *(u32*)(outLo + o) = pack_bf2(l0, l1);
                } else {
                    const size_t o = (size_t)rr * (size_t)N + col;
                    *(float2*)(outF + o) = make_float2(v0, v1);
                }
            }
        }
    }
}

// ---------------- launch ----------------------------------------------------
extern "C" void kernel_launch(void* const* d_in, const int* in_sizes, int n_in,
                              void* d_out, int out_size) {
    const float* X  = (const float*)d_in[0];
    const float* W1 = (const float*)d_in[1];
    const float* b1 = (const float*)d_in[2];
    const float* W2 = (const float*)d_in[3];
    const float* b2 = (const float*)d_in[4];
    float* out = (float*)d_out;

    void *xh, *xl, *w1h, *w1l, *w2h, *w2l, *ah, *al;
    cudaGetSymbolAddress(&xh,  g_Xhi);
    cudaGetSymbolAddress(&xl,  g_Xlo);
    cudaGetSymbolAddress(&w1h, g_W1hi);
    cudaGetSymbolAddress(&w1l, g_W1lo);
    cudaGetSymbolAddress(&w2h, g_W2hi);
    cudaGetSymbolAddress(&w2l, g_W2lo);
    cudaGetSymbolAddress(&ah,  g_Ahi);
    cudaGetSymbolAddress(&al,  g_Alo);

    cudaFuncSetAttribute(ffn_gemm_kernel<0>, cudaFuncAttributeMaxDynamicSharedMemorySize, SMEM_BYTES);
    cudaFuncSetAttribute(ffn_gemm_kernel<1>, cudaFuncAttributeMaxDynamicSharedMemorySize, SMEM_BYTES);

    {
        int n4 = M_TOT * HID / 4;
        split_kernel<<<(n4 + 255) / 256, 256>>>(X, (__nv_bfloat16*)xh, (__nv_bfloat16*)xl, n4);
    }
    {
        int n4 = INTERF * HID / 4;
        split_kernel<<<(n4 + 255) / 256, 256>>>(W1, (__nv_bfloat16*)w1h, (__nv_bfloat16*)w1l, n4);
    }
    {
        int n4 = HID * INTERF / 4;
        split_kernel<<<(n4 + 255) / 256, 256>>>(W2, (__nv_bfloat16*)w2h, (__nv_bfloat16*)w2l, n4);
    }

    // Layer 1: inter = relu(X @ W1^T + b1)  -> split bf16 planes
    dim3 g1(INTERF / 128, M_TOT / 256);
    ffn_gemm_kernel<0><<<g1, 512, SMEM_BYTES>>>(
        (const __nv_bfloat16*)xh, (const __nv_bfloat16*)xl,
        (const __nv_bfloat16*)w1h, (const __nv_bfloat16*)w1l,
        b1,
        (__nv_bfloat16*)ah, (__nv_bfloat16*)al, (float*)nullptr,
        INTERF, HID);

    // Layer 2: out = act @ W2^T + b2  -> f32
    dim3 g2(HID / 128, M_TOT / 256);
    ffn_gemm_kernel<1><<<g2, 512, SMEM_BYTES>>>(
        (const __nv_bfloat16*)ah, (const __nv_bfloat16*)al,
        (const __nv_bfloat16*)w2h, (const __nv_bfloat16*)w2l,
        b2,
        (__nv_bfloat16*)nullptr, (__nv_bfloat16*)nullptr, out,
        HID, INTERF);
}